// round 2
// baseline (speedup 1.0000x reference)
#include <cuda_runtime.h>
#include <math.h>

#define H      1024
#define BATCH  32
#define TSTEPS 512
#define INDIM  512
#define G4     (4*H)
#define NCTA   148
#define NTHR   224   // 7 warps

// ---------------- scratch (static device allocations; allowed) ----------------
__device__ float g_xz[(size_t)BATCH * TSTEPS * G4];   // 268 MB: x@W, [B*T, 4H]
__device__ float g_UT[(size_t)G4 * H];                // 16 MB: U transposed [4H][H]
__device__ float g_h[2][H * BATCH];                   // ping-pong h, layout [unit][batch]
__device__ unsigned g_bar_count;
__device__ unsigned g_bar_sense;

// ---------------- prep: zero h0 + barrier state ----------------
__global__ void zero_h_kernel() {
    int i = blockIdx.x * blockDim.x + threadIdx.x;
    if (i < 2 * H * BATCH) ((float*)g_h)[i] = 0.f;
    if (i == 0) { g_bar_count = 0u; g_bar_sense = 0u; }
}

// ---------------- transpose U [H][4H] -> UT [4H][H] ----------------
__global__ void transpose_u_kernel(const float* __restrict__ U) {
    __shared__ float tile[32][33];
    int x = blockIdx.x * 32 + threadIdx.x;   // col in U  (0..4H)
    int y = blockIdx.y * 32 + threadIdx.y;   // row in U  (0..H)
    tile[threadIdx.y][threadIdx.x] = U[(size_t)y * G4 + x];
    __syncthreads();
    int ox = blockIdx.y * 32 + threadIdx.x;  // col in UT = row in U
    int oy = blockIdx.x * 32 + threadIdx.y;  // row in UT = col in U
    g_UT[(size_t)oy * H + ox] = tile[threadIdx.x][threadIdx.y];
}

// ---------------- input GEMM: g_xz = x @ W ----------------
// M=16384 (B*T), N=4096, K=512. 128x128 tile, BK=8, 256 thr, 8x8 microtile.
__global__ __launch_bounds__(256) void sgemm_xw_kernel(const float* __restrict__ A,
                                                       const float* __restrict__ Bm) {
    const int K = INDIM, N = G4;
    __shared__ float As[8][128];
    __shared__ float Bs[8][128];
    const int tid = threadIdx.x;
    const int bm = blockIdx.y, bn = blockIdx.x;
    const int arow = tid >> 1, acol = (tid & 1) << 2;
    const int brow = tid >> 5, bcol = (tid & 31) << 2;
    const int tx = tid & 15, ty = tid >> 4;

    float acc[8][8];
#pragma unroll
    for (int i = 0; i < 8; i++)
#pragma unroll
        for (int j = 0; j < 8; j++) acc[i][j] = 0.f;

    const float* Ap = A + (size_t)(bm * 128 + arow) * K + acol;
    const float* Bp = Bm + (size_t)brow * N + bn * 128 + bcol;

    for (int k0 = 0; k0 < K; k0 += 8) {
        float4 av = *(const float4*)(Ap + k0);
        As[acol + 0][arow] = av.x;
        As[acol + 1][arow] = av.y;
        As[acol + 2][arow] = av.z;
        As[acol + 3][arow] = av.w;
        float4 bv = *(const float4*)(Bp + (size_t)k0 * N);
        *(float4*)&Bs[brow][bcol] = bv;
        __syncthreads();
#pragma unroll
        for (int kk = 0; kk < 8; kk++) {
            float ar[8], br[8];
#pragma unroll
            for (int i = 0; i < 8; i++) ar[i] = As[kk][ty * 8 + i];
#pragma unroll
            for (int j = 0; j < 8; j++) br[j] = Bs[kk][tx * 8 + j];
#pragma unroll
            for (int i = 0; i < 8; i++)
#pragma unroll
                for (int j = 0; j < 8; j++) acc[i][j] = fmaf(ar[i], br[j], acc[i][j]);
        }
        __syncthreads();
    }
    float* Cp = g_xz + (size_t)(bm * 128 + ty * 8) * N + bn * 128 + tx * 8;
#pragma unroll
    for (int i = 0; i < 8; i++)
#pragma unroll
        for (int j = 0; j < 8; j += 4) {
            float4 v = make_float4(acc[i][j], acc[i][j + 1], acc[i][j + 2], acc[i][j + 3]);
            *(float4*)(Cp + (size_t)i * N + j) = v;
        }
}

// ---------------- persistent recurrent kernel ----------------
// 148 CTAs x 224 threads (7 warps). warp -> unit u, lane -> batch b.
// h_prev staged to smem [j][b]; U read from UT (unit-stride, uniform per warp).
// Sense-reversing grid barrier; 512 barriers/launch (even) => state restores to 0.
__global__ __launch_bounds__(NTHR, 1) void lstm_rec_kernel(const float* __restrict__ bias,
                                                           float* __restrict__ out) {
    extern __shared__ float sh[];  // H*BATCH floats = 128 KB
    const int tid  = threadIdx.x;
    const int lane = tid & 31;           // batch
    const int wid  = tid >> 5;
    const int u    = blockIdx.x * 7 + wid;
    const bool act = (u < H);

    const float* Ui = 0; const float* Uf = 0; const float* Ug = 0; const float* Uo = 0;
    float bi = 0.f, bf = 0.f, bg = 0.f, bo = 0.f;
    float c = 0.f;
    if (act) {
        Ui = g_UT + (size_t)u * H;
        Uf = g_UT + (size_t)(H + u) * H;
        Ug = g_UT + (size_t)(2 * H + u) * H;
        Uo = g_UT + (size_t)(3 * H + u) * H;
        bi = bias[u]; bf = bias[H + u]; bg = bias[2 * H + u]; bo = bias[3 * H + u];
    }

    for (int t = 0; t < TSTEPS; t++) {
        // stage h_prev -> smem (L1-bypassing loads: cross-CTA producer data)
        {
            const float4* src = (const float4*)g_h[t & 1];
            float4* dst = (float4*)sh;
            for (int i = tid; i < (H * BATCH) / 4; i += NTHR) dst[i] = __ldcg(src + i);
        }
        __syncthreads();

        if (act) {
            // prefetch the precomputed input projection for this (b,t,u)
            const size_t xidx = ((size_t)lane * TSTEPS + t) * G4 + u;
            float x0 = g_xz[xidx];
            float x1 = g_xz[xidx + H];
            float x2 = g_xz[xidx + 2 * H];
            float x3 = g_xz[xidx + 3 * H];

            float a0 = 0.f, a1 = 0.f, a2 = 0.f, a3 = 0.f;
#pragma unroll 8
            for (int j = 0; j < H; j++) {
                float hv = sh[j * 32 + lane];
                a0 = fmaf(hv, Ui[j], a0);
                a1 = fmaf(hv, Uf[j], a1);
                a2 = fmaf(hv, Ug[j], a2);
                a3 = fmaf(hv, Uo[j], a3);
            }
            float zi = a0 + x0 + bi;
            float zf = a1 + x1 + bf;
            float zg = a2 + x2 + bg;
            float zo = a3 + x3 + bo;

            float ig = 1.f / (1.f + __expf(-zi));
            float fg = 1.f / (1.f + __expf(-zf));
            float gg = tanhf(zg);
            float og = 1.f / (1.f + __expf(-zo));

            c = fg * c + ig * gg;
            float hval = og * tanhf(c);

            out[((size_t)lane * TSTEPS + t) * H + u] = hval;        // [B,T,H]
            g_h[(t + 1) & 1][u * 32 + lane] = hval;                 // [unit][batch]
        }

        // ---- grid barrier (sense-reversing) ----
        __threadfence();
        __syncthreads();
        if (tid == 0) {
            unsigned tgt = (unsigned)((t & 1) ^ 1);
            unsigned pos = atomicAdd(&g_bar_count, 1u);
            if (pos == (unsigned)gridDim.x - 1u) {
                atomicExch(&g_bar_count, 0u);
                __threadfence();
                atomicExch(&g_bar_sense, tgt);
            } else {
                while (atomicAdd(&g_bar_sense, 0u) != tgt) __nanosleep(32);
            }
            __threadfence();
        }
        __syncthreads();
    }
}

// ---------------- launch ----------------
extern "C" void kernel_launch(void* const* d_in, const int* in_sizes, int n_in,
                              void* d_out, int out_size) {
    const float* x    = (const float*)d_in[0];  // [32,512,512]
    const float* W    = (const float*)d_in[1];  // [512,4096]
    const float* U    = (const float*)d_in[2];  // [1024,4096]
    const float* bias = (const float*)d_in[3];  // [4096]
    float* out = (float*)d_out;                 // [32,512,1024]

    cudaFuncSetAttribute(lstm_rec_kernel, cudaFuncAttributeMaxDynamicSharedMemorySize,
                         H * BATCH * (int)sizeof(float));

    zero_h_kernel<<<(2 * H * BATCH + 255) / 256, 256>>>();
    transpose_u_kernel<<<dim3(G4 / 32, H / 32), dim3(32, 32)>>>(U);
    sgemm_xw_kernel<<<dim3(G4 / 128, (BATCH * TSTEPS) / 128), 256>>>(x, W);
    lstm_rec_kernel<<<NCTA, NTHR, H * BATCH * (int)sizeof(float)>>>(bias, out);
}

// round 3
// speedup vs baseline: 1.8015x; 1.8015x over previous
#include <cuda_runtime.h>
#include <math.h>

#define H      1024
#define BATCH  32
#define TSTEPS 512
#define INDIM  512
#define G4     (4*H)
#define NCTA2  128
#define NTHR2  256   // 8 warps

// ---------------- scratch (static device allocations; allowed) ----------------
__device__ float g_xz[(size_t)BATCH * TSTEPS * G4];   // 268 MB: x@W, [B*T, 4H]
__device__ float g_UT[(size_t)G4 * H];                // 16 MB: U transposed [4H][H]
__device__ float g_h[2][BATCH * H];                   // ping-pong h, layout [b][j]
__device__ unsigned g_bar_count;
__device__ unsigned g_bar_sense;

// ---------------- f32x2 packed helpers (sm_100 Blackwell) ----------------
__device__ __forceinline__ void fma2(unsigned long long& d, unsigned long long a,
                                     unsigned long long b) {
    asm("fma.rn.f32x2 %0, %1, %2, %0;" : "+l"(d) : "l"(a), "l"(b));
}
__device__ __forceinline__ float2 ull2f2(unsigned long long v) {
    float2 f;
    asm("mov.b64 {%0, %1}, %2;" : "=f"(f.x), "=f"(f.y) : "l"(v));
    return f;
}
__device__ __forceinline__ unsigned long long packdup(float a) {
    unsigned long long d;
    asm("mov.b64 %0, {%1, %1};" : "=l"(d) : "f"(a));
    return d;
}

// ---------------- prep: zero h0 + barrier state ----------------
__global__ void zero_h_kernel() {
    int i = blockIdx.x * blockDim.x + threadIdx.x;
    if (i < 2 * BATCH * H) ((float*)g_h)[i] = 0.f;
    if (i == 0) { g_bar_count = 0u; g_bar_sense = 0u; }
}

// ---------------- transpose U [H][4H] -> UT [4H][H] ----------------
__global__ void transpose_u_kernel(const float* __restrict__ U) {
    __shared__ float tile[32][33];
    int x = blockIdx.x * 32 + threadIdx.x;
    int y = blockIdx.y * 32 + threadIdx.y;
    tile[threadIdx.y][threadIdx.x] = U[(size_t)y * G4 + x];
    __syncthreads();
    int ox = blockIdx.y * 32 + threadIdx.x;
    int oy = blockIdx.x * 32 + threadIdx.y;
    g_UT[(size_t)oy * H + ox] = tile[threadIdx.x][threadIdx.y];
}

// ---------------- input GEMM: g_xz = x @ W (f32x2 packed) ----------------
// M=16384, N=4096, K=512. 128x128 tile, BK=8, 256 thr, 8x8 microtile,
// accumulators packed over row pairs.
__global__ __launch_bounds__(256) void sgemm_xw_kernel(const float* __restrict__ A,
                                                       const float* __restrict__ Bm) {
    const int K = INDIM, N = G4;
    __shared__ float As[8][128];
    __shared__ float Bs[8][128];
    const int tid = threadIdx.x;
    const int bm = blockIdx.y, bn = blockIdx.x;
    const int arow = tid >> 1, acol = (tid & 1) << 2;
    const int brow = tid >> 5, bcol = (tid & 31) << 2;
    const int tx = tid & 15, ty = tid >> 4;

    unsigned long long acc2[4][8];   // (rows 2i,2i+1) x cols j
#pragma unroll
    for (int i = 0; i < 4; i++)
#pragma unroll
        for (int j = 0; j < 8; j++) acc2[i][j] = 0ull;

    const float* Ap = A + (size_t)(bm * 128 + arow) * K + acol;
    const float* Bp = Bm + (size_t)brow * N + bn * 128 + bcol;

    for (int k0 = 0; k0 < K; k0 += 8) {
        float4 av = *(const float4*)(Ap + k0);
        As[acol + 0][arow] = av.x;
        As[acol + 1][arow] = av.y;
        As[acol + 2][arow] = av.z;
        As[acol + 3][arow] = av.w;
        float4 bv = *(const float4*)(Bp + (size_t)k0 * N);
        *(float4*)&Bs[brow][bcol] = bv;
        __syncthreads();
#pragma unroll
        for (int kk = 0; kk < 8; kk++) {
            // a: 8 consecutive rows -> 4 packed pairs
            ulonglong2 a01 = *(const ulonglong2*)&As[kk][ty * 8];
            ulonglong2 a23 = *(const ulonglong2*)&As[kk][ty * 8 + 4];
            unsigned long long a2[4] = {a01.x, a01.y, a23.x, a23.y};
            float4 b0 = *(const float4*)&Bs[kk][tx * 8];
            float4 b1 = *(const float4*)&Bs[kk][tx * 8 + 4];
            unsigned long long b2[8];
            b2[0] = packdup(b0.x); b2[1] = packdup(b0.y);
            b2[2] = packdup(b0.z); b2[3] = packdup(b0.w);
            b2[4] = packdup(b1.x); b2[5] = packdup(b1.y);
            b2[6] = packdup(b1.z); b2[7] = packdup(b1.w);
#pragma unroll
            for (int i = 0; i < 4; i++)
#pragma unroll
                for (int j = 0; j < 8; j++) fma2(acc2[i][j], a2[i], b2[j]);
        }
        __syncthreads();
    }
    float* Cp = g_xz + (size_t)(bm * 128 + ty * 8) * N + bn * 128 + tx * 8;
#pragma unroll
    for (int i = 0; i < 4; i++) {
        float4 r0a, r0b, r1a, r1b;
        float2 p;
        p = ull2f2(acc2[i][0]); r0a.x = p.x; r1a.x = p.y;
        p = ull2f2(acc2[i][1]); r0a.y = p.x; r1a.y = p.y;
        p = ull2f2(acc2[i][2]); r0a.z = p.x; r1a.z = p.y;
        p = ull2f2(acc2[i][3]); r0a.w = p.x; r1a.w = p.y;
        p = ull2f2(acc2[i][4]); r0b.x = p.x; r1b.x = p.y;
        p = ull2f2(acc2[i][5]); r0b.y = p.x; r1b.y = p.y;
        p = ull2f2(acc2[i][6]); r0b.z = p.x; r1b.z = p.y;
        p = ull2f2(acc2[i][7]); r0b.w = p.x; r1b.w = p.y;
        *(float4*)(Cp + (size_t)(2 * i) * N)     = r0a;
        *(float4*)(Cp + (size_t)(2 * i) * N + 4) = r0b;
        *(float4*)(Cp + (size_t)(2 * i + 1) * N)     = r1a;
        *(float4*)(Cp + (size_t)(2 * i + 1) * N + 4) = r1b;
    }
}

// ---------------- persistent recurrent kernel (register-resident U) ----------------
// 128 CTAs x 256 thr (8 warps). Warp w -> unit u = bid*8+w (4 gate rows).
// lane: r = lane>>3 (gate), cs = lane&7 (col slice {j: (j>>2)&7 == cs}).
// Each thread: 128 U floats in regs as 64 f32x2 pairs. h staged to smem [b][j].
__global__ __launch_bounds__(NTHR2, 1) void lstm_rec2(const float* __restrict__ bias,
                                                      const float* __restrict__ xz,
                                                      float* __restrict__ out) {
    extern __shared__ float sh[];
    float* sh_h = sh;                 // [32][1024] = 128 KB
    float* zbuf = sh + 32 * H;        // [8 warps][4 gates][33]
    const int tid  = threadIdx.x;
    const int lane = tid & 31;
    const int w    = tid >> 5;
    const int r    = lane >> 3;
    const int cs4  = (lane & 7) << 2;
    const int u    = blockIdx.x * 8 + w;

    // U slice -> registers (once)
    unsigned long long ur2[64];
    {
        const float* Up = g_UT + ((size_t)r * H + u) * H + cs4;
#pragma unroll
        for (int q = 0; q < 32; q++) {
            ulonglong2 v = *(const ulonglong2*)(Up + q * 32);
            ur2[2 * q]     = v.x;
            ur2[2 * q + 1] = v.y;
        }
    }
    const float b_i = bias[u], b_f = bias[H + u], b_g = bias[2 * H + u], b_o = bias[3 * H + u];
    float c = 0.f;

    // stage h[0] (zeros)
    {
        const float4* src = (const float4*)g_h[0];
        float4* dst = (float4*)sh_h;
#pragma unroll
        for (int i = 0; i < 32; i++) dst[tid + i * NTHR2] = __ldcg(src + tid + i * NTHR2);
    }

    for (int t = 0; t < TSTEPS; t++) {
        __syncthreads();  // staging complete

        // hoist input-projection loads (lane plays batch role here)
        const size_t xbase = ((size_t)lane * TSTEPS + t) * (size_t)G4 + u;
        const float x0 = xz[xbase];
        const float x1 = xz[xbase + H];
        const float x2 = xz[xbase + 2 * H];
        const float x3 = xz[xbase + 3 * H];

        // recurrent GEMV: 4 batch-chunks of 8
        for (int ch = 0; ch < 4; ch++) {
            const int b0 = ch << 3;
            unsigned long long acc2[8];
#pragma unroll
            for (int b = 0; b < 8; b++) acc2[b] = 0ull;
            const float* hp = sh_h + b0 * H + cs4;
#pragma unroll
            for (int q = 0; q < 32; q++) {
#pragma unroll
                for (int b = 0; b < 8; b++) {
                    ulonglong2 hv = *(const ulonglong2*)(hp + b * H + q * 32);
                    fma2(acc2[b], hv.x, ur2[2 * q]);
                    fma2(acc2[b], hv.y, ur2[2 * q + 1]);
                }
            }
            float ared[8];
#pragma unroll
            for (int b = 0; b < 8; b++) {
                float2 p = ull2f2(acc2[b]);
                ared[b] = p.x + p.y;
            }
#pragma unroll
            for (int m = 1; m < 8; m <<= 1)
#pragma unroll
                for (int b = 0; b < 8; b++)
                    ared[b] += __shfl_xor_sync(0xffffffffu, ared[b], m);
            // lane (r, cs) commits value for b = b0 + cs
            const int csl = lane & 7;
            float v = ared[0];
            if (csl == 1) v = ared[1];
            if (csl == 2) v = ared[2];
            if (csl == 3) v = ared[3];
            if (csl == 4) v = ared[4];
            if (csl == 5) v = ared[5];
            if (csl == 6) v = ared[6];
            if (csl == 7) v = ared[7];
            zbuf[w * 132 + r * 33 + b0 + csl] = v;
        }
        __syncwarp();

        // pointwise (lane = batch b)
        const float zi = zbuf[w * 132 + lane] + x0 + b_i;
        const float zf = zbuf[w * 132 + 33 + lane] + x1 + b_f;
        const float zg = zbuf[w * 132 + 66 + lane] + x2 + b_g;
        const float zo = zbuf[w * 132 + 99 + lane] + x3 + b_o;

        const float ig = 1.f / (1.f + __expf(-zi));
        const float fg = 1.f / (1.f + __expf(-zf));
        const float gg = tanhf(zg);
        const float og = 1.f / (1.f + __expf(-zo));

        c = fg * c + ig * gg;
        const float hval = og * tanhf(c);

        out[((size_t)lane * TSTEPS + t) * H + u] = hval;
        g_h[(t + 1) & 1][(size_t)lane * H + u] = hval;

        // ---- grid barrier (sense-reversing; 512/launch => state restores) ----
        __threadfence();
        __syncthreads();
        if (tid == 0) {
            unsigned tgt = (unsigned)((t & 1) ^ 1);
            unsigned pos = atomicAdd(&g_bar_count, 1u);
            if (pos == (unsigned)gridDim.x - 1u) {
                atomicExch(&g_bar_count, 0u);
                __threadfence();
                atomicExch(&g_bar_sense, tgt);
            } else {
                while (atomicAdd(&g_bar_sense, 0u) != tgt) __nanosleep(32);
            }
            __threadfence();
        }
        __syncthreads();

        // stage next h
        {
            const float4* src = (const float4*)g_h[(t + 1) & 1];
            float4* dst = (float4*)sh_h;
#pragma unroll
            for (int i = 0; i < 32; i++) dst[tid + i * NTHR2] = __ldcg(src + tid + i * NTHR2);
        }
    }
}

// ---------------- launch ----------------
extern "C" void kernel_launch(void* const* d_in, const int* in_sizes, int n_in,
                              void* d_out, int out_size) {
    const float* x    = (const float*)d_in[0];  // [32,512,512]
    const float* W    = (const float*)d_in[1];  // [512,4096]
    const float* U    = (const float*)d_in[2];  // [1024,4096]
    const float* bias = (const float*)d_in[3];  // [4096]
    float* out = (float*)d_out;                 // [32,512,1024]

    static const int rec_smem = (32 * H + 8 * 132) * (int)sizeof(float);
    cudaFuncSetAttribute(lstm_rec2, cudaFuncAttributeMaxDynamicSharedMemorySize, rec_smem);

    float* xz_dev = nullptr;
    cudaGetSymbolAddress((void**)&xz_dev, g_xz);

    zero_h_kernel<<<(2 * BATCH * H + 255) / 256, 256>>>();
    transpose_u_kernel<<<dim3(G4 / 32, H / 32), dim3(32, 32)>>>(U);
    sgemm_xw_kernel<<<dim3(G4 / 128, (BATCH * TSTEPS) / 128), 256>>>(x, W);
    lstm_rec2<<<NCTA2, NTHR2, rec_smem>>>(bias, xz_dev, out);
}

// round 5
// speedup vs baseline: 2.9500x; 1.6375x over previous
#include <cuda_runtime.h>
#include <math.h>

#define H      1024
#define BATCH  32
#define TSTEPS 512
#define INDIM  512
#define G4     (4*H)
#define NCTA3  128
#define NTHR3  256   // 8 warps; warp = 1 unit

// ---------------- scratch ----------------
__device__ float g_xz[(size_t)BATCH * TSTEPS * G4];   // 268 MB: x@W, [B*T, 4H]
__device__ float g_UT[(size_t)G4 * H];                // 16 MB: U transposed [4H][H]
__device__ float g_h[2][BATCH * H];                   // ping-pong h, [b][j]
__device__ unsigned g_bar_count;
__device__ unsigned g_bar_sense;

// ---------------- f32x2 helpers ----------------
__device__ __forceinline__ void fma2(unsigned long long& d, unsigned long long a,
                                     unsigned long long b) {
    asm("fma.rn.f32x2 %0, %1, %2, %0;" : "+l"(d) : "l"(a), "l"(b));
}
__device__ __forceinline__ float hsum2(unsigned long long v) {
    float x, y;
    asm("mov.b64 {%0, %1}, %2;" : "=f"(x), "=f"(y) : "l"(v));
    return x + y;
}
__device__ __forceinline__ unsigned long long packdup(float a) {
    unsigned long long d;
    asm("mov.b64 %0, {%1, %1};" : "=l"(d) : "f"(a));
    return d;
}

// ---------------- prep ----------------
__global__ void zero_h_kernel() {
    int i = blockIdx.x * blockDim.x + threadIdx.x;
    if (i < 2 * BATCH * H) ((float*)g_h)[i] = 0.f;
    if (i == 0) { g_bar_count = 0u; g_bar_sense = 0u; }
}

__global__ void transpose_u_kernel(const float* __restrict__ U) {
    __shared__ float tile[32][33];
    int x = blockIdx.x * 32 + threadIdx.x;
    int y = blockIdx.y * 32 + threadIdx.y;
    tile[threadIdx.y][threadIdx.x] = U[(size_t)y * G4 + x];
    __syncthreads();
    int ox = blockIdx.y * 32 + threadIdx.x;
    int oy = blockIdx.x * 32 + threadIdx.y;
    g_UT[(size_t)oy * H + ox] = tile[threadIdx.x][threadIdx.y];
}

// ---------------- input GEMM: g_xz = x @ W (f32x2 packed) ----------------
__global__ __launch_bounds__(256) void sgemm_xw_kernel(const float* __restrict__ A,
                                                       const float* __restrict__ Bm) {
    const int K = INDIM, N = G4;
    __shared__ float As[8][128];
    __shared__ float Bs[8][128];
    const int tid = threadIdx.x;
    const int bm = blockIdx.y, bn = blockIdx.x;
    const int arow = tid >> 1, acol = (tid & 1) << 2;
    const int brow = tid >> 5, bcol = (tid & 31) << 2;
    const int tx = tid & 15, ty = tid >> 4;

    unsigned long long acc2[4][8];
#pragma unroll
    for (int i = 0; i < 4; i++)
#pragma unroll
        for (int j = 0; j < 8; j++) acc2[i][j] = 0ull;

    const float* Ap = A + (size_t)(bm * 128 + arow) * K + acol;
    const float* Bp = Bm + (size_t)brow * N + bn * 128 + bcol;

    for (int k0 = 0; k0 < K; k0 += 8) {
        float4 av = *(const float4*)(Ap + k0);
        As[acol + 0][arow] = av.x;
        As[acol + 1][arow] = av.y;
        As[acol + 2][arow] = av.z;
        As[acol + 3][arow] = av.w;
        float4 bv = *(const float4*)(Bp + (size_t)k0 * N);
        *(float4*)&Bs[brow][bcol] = bv;
        __syncthreads();
#pragma unroll
        for (int kk = 0; kk < 8; kk++) {
            ulonglong2 a01 = *(const ulonglong2*)&As[kk][ty * 8];
            ulonglong2 a23 = *(const ulonglong2*)&As[kk][ty * 8 + 4];
            unsigned long long a2[4] = {a01.x, a01.y, a23.x, a23.y};
            float4 b0 = *(const float4*)&Bs[kk][tx * 8];
            float4 b1 = *(const float4*)&Bs[kk][tx * 8 + 4];
            unsigned long long b2[8];
            b2[0] = packdup(b0.x); b2[1] = packdup(b0.y);
            b2[2] = packdup(b0.z); b2[3] = packdup(b0.w);
            b2[4] = packdup(b1.x); b2[5] = packdup(b1.y);
            b2[6] = packdup(b1.z); b2[7] = packdup(b1.w);
#pragma unroll
            for (int i = 0; i < 4; i++)
#pragma unroll
                for (int j = 0; j < 8; j++) fma2(acc2[i][j], a2[i], b2[j]);
        }
        __syncthreads();
    }
    float* Cp = g_xz + (size_t)(bm * 128 + ty * 8) * N + bn * 128 + tx * 8;
#pragma unroll
    for (int i = 0; i < 4; i++) {
        float r0[8], r1[8];
#pragma unroll
        for (int j = 0; j < 8; j++) {
            float x, y;
            asm("mov.b64 {%0, %1}, %2;" : "=f"(x), "=f"(y) : "l"(acc2[i][j]));
            r0[j] = x; r1[j] = y;
        }
        *(float4*)(Cp + (size_t)(2 * i) * N)     = make_float4(r0[0], r0[1], r0[2], r0[3]);
        *(float4*)(Cp + (size_t)(2 * i) * N + 4) = make_float4(r0[4], r0[5], r0[6], r0[7]);
        *(float4*)(Cp + (size_t)(2 * i + 1) * N)     = make_float4(r1[0], r1[1], r1[2], r1[3]);
        *(float4*)(Cp + (size_t)(2 * i + 1) * N + 4) = make_float4(r1[4], r1[5], r1[6], r1[7]);
    }
}

// ---------------- persistent recurrent kernel v4 ----------------
// 128 CTAs x 256 thr (8 warps). Warp w -> unit u = bid*8+w, ALL 4 gates.
// Lane j-slice: j in { lane*4 + m*128 + e : m=0..7, e=0..3 } (strided; every
// LDS.128 is 32 lanes x contiguous 16B = conflict-free, zero gate duplication).
// U slice in registers: 4 gates x 32 j = 128 floats = 64 f32x2.
// Cross-lane reduction: gate-fold shuffle (gates mapped onto lane bits 4,3):
//   stage xor16 (2 shfl) + stage xor8 (1 shfl) + butterfly xor4/2/1 (3 shfl)
//   + 4 shfl.idx gather = 10 SHFL per batch for all 4 gates.
__global__ __launch_bounds__(NTHR3, 1) void lstm_rec4(const float* __restrict__ bias,
                                                      const float* __restrict__ xz,
                                                      float* __restrict__ out) {
    extern __shared__ float sh_h[];   // [32][1024] = 128 KB
    const int tid  = threadIdx.x;
    const int lane = tid & 31;
    const int w    = tid >> 5;
    const int u    = blockIdx.x * 8 + w;

    // ---- U slice -> registers (once)
    unsigned long long ur2[4][16];
#pragma unroll
    for (int g = 0; g < 4; g++)
#pragma unroll
        for (int m = 0; m < 8; m++) {
            ulonglong2 v = *(const ulonglong2*)(g_UT + ((size_t)(g * H + u)) * H
                                                + m * 128 + lane * 4);
            ur2[g][2 * m]     = v.x;
            ur2[g][2 * m + 1] = v.y;
        }
    const float b_i = bias[u], b_f = bias[H + u], b_g = bias[2 * H + u], b_o = bias[3 * H + u];
    float c = 0.f;

    const bool hi4 = (lane & 16) != 0;
    const bool hi3 = (lane & 8) != 0;

    // stage h[0] (zeros)
    {
        const float4* src = (const float4*)g_h[0];
        float4* dst = (float4*)sh_h;
#pragma unroll
        for (int i = 0; i < 32; i++) dst[tid + i * NTHR3] = __ldcg(src + tid + i * NTHR3);
    }

    for (int t = 0; t < TSTEPS; t++) {
        __syncthreads();  // staging complete

        // input-projection prefetch (lane plays batch role)
        const size_t xbase = ((size_t)lane * TSTEPS + t) * (size_t)G4 + u;
        const float x0 = xz[xbase];
        const float x1 = xz[xbase + H];
        const float x2 = xz[xbase + 2 * H];
        const float x3 = xz[xbase + 3 * H];

        float zi = 0.f, zf = 0.f, zg = 0.f, zo = 0.f;

#pragma unroll 4
        for (int b = 0; b < BATCH; b++) {
            unsigned long long a0 = 0ull, a1 = 0ull, a2 = 0ull, a3 = 0ull;
            const float* hb = sh_h + b * H + lane * 4;
#pragma unroll
            for (int m = 0; m < 8; m++) {
                ulonglong2 hv = *(const ulonglong2*)(hb + m * 128);
                fma2(a0, hv.x, ur2[0][2 * m]);
                fma2(a1, hv.x, ur2[1][2 * m]);
                fma2(a2, hv.x, ur2[2][2 * m]);
                fma2(a3, hv.x, ur2[3][2 * m]);
                fma2(a0, hv.y, ur2[0][2 * m + 1]);
                fma2(a1, hv.y, ur2[1][2 * m + 1]);
                fma2(a2, hv.y, ur2[2][2 * m + 1]);
                fma2(a3, hv.y, ur2[3][2 * m + 1]);
            }
            float s0 = hsum2(a0), s1 = hsum2(a1), s2 = hsum2(a2), s3 = hsum2(a3);

            // gate-fold reduction: gates -> lane bits 4,3
            // stage xor16: bit4=0 keeps gates {0,1}, bit4=1 keeps {2,3}
            float t0 = hi4 ? s0 : s2;
            float t1 = hi4 ? s1 : s3;
            float r0 = __shfl_xor_sync(0xffffffffu, t0, 16);
            float r1 = __shfl_xor_sync(0xffffffffu, t1, 16);
            float u0 = (hi4 ? s2 : s0) + r0;
            float u1 = (hi4 ? s3 : s1) + r1;
            // stage xor8: bit3 selects within pair
            float t2 = hi3 ? u0 : u1;
            float r2 = __shfl_xor_sync(0xffffffffu, t2, 8);
            float v = (hi3 ? u1 : u0) + r2;   // gate = (lane>>3)&3
            // butterfly over bits 2..0
            v += __shfl_xor_sync(0xffffffffu, v, 4);
            v += __shfl_xor_sync(0xffffffffu, v, 2);
            v += __shfl_xor_sync(0xffffffffu, v, 1);
            // gather the 4 gates onto lane b
            const int bl = b & 7;
            float gi = __shfl_sync(0xffffffffu, v, bl);
            float gf = __shfl_sync(0xffffffffu, v, 8 + bl);
            float gg = __shfl_sync(0xffffffffu, v, 16 + bl);
            float go = __shfl_sync(0xffffffffu, v, 24 + bl);
            if (lane == b) { zi = gi; zf = gf; zg = gg; zo = go; }
        }

        // pointwise (lane = batch)
        zi += x0 + b_i;
        zf += x1 + b_f;
        zg += x2 + b_g;
        zo += x3 + b_o;

        const float ig = 1.f / (1.f + __expf(-zi));
        const float fg = 1.f / (1.f + __expf(-zf));
        const float gv = tanhf(zg);
        const float og = 1.f / (1.f + __expf(-zo));

        c = fg * c + ig * gv;
        const float hval = og * tanhf(c);

        out[((size_t)lane * TSTEPS + t) * H + u] = hval;
        g_h[(t + 1) & 1][(size_t)lane * H + u] = hval;

        // ---- grid barrier (sense-reversing; even count/launch => state restores) ----
        __threadfence();
        __syncthreads();
        if (tid == 0) {
            unsigned tgt = (unsigned)((t & 1) ^ 1);
            unsigned pos = atomicAdd(&g_bar_count, 1u);
            if (pos == (unsigned)gridDim.x - 1u) {
                atomicExch(&g_bar_count, 0u);
                __threadfence();
                atomicExch(&g_bar_sense, tgt);
            } else {
                while (atomicAdd(&g_bar_sense, 0u) != tgt) __nanosleep(32);
            }
            __threadfence();
        }
        __syncthreads();

        // stage next h
        {
            const float4* src = (const float4*)g_h[(t + 1) & 1];
            float4* dst = (float4*)sh_h;
#pragma unroll
            for (int i = 0; i < 32; i++) dst[tid + i * NTHR3] = __ldcg(src + tid + i * NTHR3);
        }
    }
}

// ---------------- launch ----------------
extern "C" void kernel_launch(void* const* d_in, const int* in_sizes, int n_in,
                              void* d_out, int out_size) {
    const float* x    = (const float*)d_in[0];  // [32,512,512]
    const float* W    = (const float*)d_in[1];  // [512,4096]
    const float* U    = (const float*)d_in[2];  // [1024,4096]
    const float* bias = (const float*)d_in[3];  // [4096]
    float* out = (float*)d_out;                 // [32,512,1024]

    static const int rec_smem = 32 * H * (int)sizeof(float);
    cudaFuncSetAttribute(lstm_rec4, cudaFuncAttributeMaxDynamicSharedMemorySize, rec_smem);

    float* xz_dev = nullptr;
    cudaGetSymbolAddress((void**)&xz_dev, g_xz);

    zero_h_kernel<<<(2 * BATCH * H + 255) / 256, 256>>>();
    transpose_u_kernel<<<dim3(G4 / 32, H / 32), dim3(32, 32)>>>(U);
    sgemm_xw_kernel<<<dim3(G4 / 128, (BATCH * TSTEPS) / 128), 256>>>(x, W);
    lstm_rec4<<<NCTA3, NTHR3, rec_smem>>>(bias, xz_dev, out);
}